// round 13
// baseline (speedup 1.0000x reference)
#include <cuda_runtime.h>
#include <cuda_fp16.h>
#include <math.h>
#include <cstdint>

// Problem constants
#define Bb   2
#define Tt   2048
#define NE   1024
#define NH   16
#define NKV  4
#define HD   64
#define GC   32
#define WIN  1024
#define BT   (Bb*Tt)          // 4096
#define QKDIM (NH*HD)         // 1024
#define KVDIM (NKV*HD)        // 256

// fp16 split planes for GEMMs (A = hi+lo, B = hi only)
__device__ __align__(256) __half g_xh[BT * NE],  g_xl[BT * NE];
__device__ __align__(256) __half g_yh[BT * NE],  g_yl[BT * NE];
__device__ __align__(256) __half g_wqh[QKDIM * NE];
__device__ __align__(256) __half g_wkh[KVDIM * NE];
__device__ __align__(256) __half g_wvh[KVDIM * NE];
__device__ __align__(256) __half g_woh[NE * NE];

// fp16 planes for attention, head-major: q hi+lo, k/v hi only
__device__ __align__(256) __half g_qph[BT * QKDIM], g_qpl[BT * QKDIM];
__device__ __align__(256) __half g_kph[BT * KVDIM];
__device__ __align__(256) __half g_vph[BT * KVDIM];

// gate values: [BT][NKV]
__device__ float g_gate[BT * NKV];

// ---------------------------------------------------------------------------
// Helpers
// ---------------------------------------------------------------------------
__device__ __forceinline__ uint32_t smem_u32(const void* p) {
    uint32_t a;
    asm("{ .reg .u64 t; cvta.to.shared.u64 t, %1; cvt.u32.u64 %0, t; }" : "=r"(a) : "l"(p));
    return a;
}
__device__ __forceinline__ void cp16(uint32_t s, const void* g) {
    asm volatile("cp.async.cg.shared.global [%0], [%1], 16;" :: "r"(s), "l"(g));
}
#define CP_COMMIT() asm volatile("cp.async.commit_group;" ::: "memory")
#define CP_WAIT0()  asm volatile("cp.async.wait_group 0;" ::: "memory")
#define CP_WAIT1()  asm volatile("cp.async.wait_group 1;" ::: "memory")

__device__ __forceinline__ void ldsm_x4(uint32_t& r0, uint32_t& r1, uint32_t& r2, uint32_t& r3,
                                        uint32_t addr) {
    asm volatile("ldmatrix.sync.aligned.m8n8.x4.shared.b16 {%0,%1,%2,%3}, [%4];"
                 : "=r"(r0), "=r"(r1), "=r"(r2), "=r"(r3) : "r"(addr));
}
__device__ __forceinline__ void ldsm_x4t(uint32_t& r0, uint32_t& r1, uint32_t& r2, uint32_t& r3,
                                         uint32_t addr) {
    asm volatile("ldmatrix.sync.aligned.m8n8.x4.trans.shared.b16 {%0,%1,%2,%3}, [%4];"
                 : "=r"(r0), "=r"(r1), "=r"(r2), "=r"(r3) : "r"(addr));
}
__device__ __forceinline__ void mma_f16(float* c, const uint32_t* a, const uint32_t* b) {
    asm volatile("mma.sync.aligned.m16n8k16.row.col.f32.f16.f16.f32 "
                 "{%0,%1,%2,%3}, {%4,%5,%6,%7}, {%8,%9}, {%0,%1,%2,%3};"
                 : "+f"(c[0]), "+f"(c[1]), "+f"(c[2]), "+f"(c[3])
                 : "r"(a[0]), "r"(a[1]), "r"(a[2]), "r"(a[3]), "r"(b[0]), "r"(b[1]));
}
__device__ __forceinline__ uint32_t pack_h2(__half a, __half b) {
    __half2 t = __halves2half2(a, b);
    return *reinterpret_cast<uint32_t*>(&t);
}
__device__ __forceinline__ void split2h(float a, float b, uint32_t& h, uint32_t& l) {
    __half ha = __float2half_rn(a), hb = __float2half_rn(b);
    h = pack_h2(ha, hb);
    l = pack_h2(__float2half_rn(a - __half2float(ha)),
                __float2half_rn(b - __half2float(hb)));
}
__device__ __forceinline__ float warp_sum(float v) {
    #pragma unroll
    for (int off = 16; off; off >>= 1) v += __shfl_xor_sync(0xffffffffu, v, off);
    return v;
}

// ---------------------------------------------------------------------------
// Split fp32 -> fp16 hi/lo planes
// ---------------------------------------------------------------------------
__global__ __launch_bounds__(256) void split_kernel(const float4* __restrict__ in,
                                                    __half* __restrict__ hi,
                                                    __half* __restrict__ lo,
                                                    int n4) {
    int i = blockIdx.x * 256 + threadIdx.x;
    if (i >= n4) return;
    float4 v = in[i];
    float a[4] = {v.x, v.y, v.z, v.w};
    __half h[4], l[4];
    #pragma unroll
    for (int j = 0; j < 4; j++) {
        h[j] = __float2half_rn(a[j]);
        l[j] = __float2half_rn(a[j] - __half2float(h[j]));
    }
    __half2* h2 = (__half2*)(hi + 4 * (size_t)i);
    __half2* l2 = (__half2*)(lo + 4 * (size_t)i);
    h2[0] = __halves2half2(h[0], h[1]);
    h2[1] = __halves2half2(h[2], h[3]);
    l2[0] = __halves2half2(l[0], l[1]);
    l2[1] = __halves2half2(l[2], l[3]);
}

// Merged transpose for all 4 weights (z-select), fp16 hi-plane only.
__global__ __launch_bounds__(256) void tsplit_all(const float* __restrict__ Wq,
                                                  const float* __restrict__ Wk,
                                                  const float* __restrict__ Wv,
                                                  const float* __restrict__ Wo,
                                                  __half* __restrict__ qh_, __half* __restrict__ kh_,
                                                  __half* __restrict__ vh_, __half* __restrict__ oh_) {
    const int z = blockIdx.z;
    const float* W; __half* hi; int Ncols;
    if (z == 0)      { W = Wq; hi = qh_; Ncols = QKDIM; }
    else if (z == 1) { W = Wk; hi = kh_; Ncols = KVDIM; }
    else if (z == 2) { W = Wv; hi = vh_; Ncols = KVDIM; }
    else             { W = Wo; hi = oh_; Ncols = NE; }
    if (blockIdx.x * 32 >= Ncols) return;

    __shared__ float t[32][33];
    const int n0 = blockIdx.x * 32, k0 = blockIdx.y * 32;
    const int tx = threadIdx.x, ty = threadIdx.y;   // 32 x 8
    #pragma unroll
    for (int j = 0; j < 32; j += 8)
        t[ty + j][tx] = W[(size_t)(k0 + ty + j) * Ncols + n0 + tx];
    __syncthreads();
    #pragma unroll
    for (int j = 0; j < 32; j += 8) {
        size_t o = (size_t)(n0 + ty + j) * NE + k0 + tx;
        hi[o] = __float2half_rn(t[tx][ty + j]);
    }
}

// Gate precompute
__global__ __launch_bounds__(256) void gate_kernel(const float* __restrict__ x,
                                                   const float* __restrict__ Wg,
                                                   float* __restrict__ gate) {
    const int bt = blockIdx.x * 8 + (threadIdx.x >> 5);
    const int lane = threadIdx.x & 31;
    const float xv = x[(size_t)bt * NE + lane];
    #pragma unroll
    for (int kvh = 0; kvh < NKV; kvh++) {
        float dot = warp_sum(xv * Wg[lane * NKV + kvh]);
        if (lane == 0) gate[bt * NKV + kvh] = 2.f / (1.f + __expf(-dot));
    }
}

// ---------------------------------------------------------------------------
// mma.sync 2-MMA fp16 GEMM mainloop, 3-stage cp.async pipeline.
// ---------------------------------------------------------------------------
#define TILE_B   10240              // 128 * 80
#define STAGE_B  (3 * TILE_B)       // 30720 per stage
#define GEMM_SMEM (3 * STAGE_B)     // 92160 (3 stages)

__device__ __forceinline__ void gemm_mainloop(const __half* __restrict__ Ah,
                                              const __half* __restrict__ Al,
                                              const __half* __restrict__ Bh,
                                              int bm, int bn, int K,
                                              uint32_t sbase, float c[2][8][4]) {
    const int tid = threadIdx.x;
    const int lane = tid & 31, wid = tid >> 5;
    const int warp_m = (wid & 3) * 32;
    const int warp_n = (wid >> 2) * 64;

    const __half* gbase[3] = {Ah + (size_t)bm * K, Al + (size_t)bm * K, Bh + (size_t)bn * K};

    #pragma unroll
    for (int mt = 0; mt < 2; mt++)
        #pragma unroll
        for (int nt = 0; nt < 8; nt++)
            #pragma unroll
            for (int e = 0; e < 4; e++) c[mt][nt][e] = 0.f;

    const uint32_t aRow = (uint32_t)(lane & 15), aChunk = (uint32_t)(lane >> 4);
    const uint32_t bRow = (uint32_t)(((lane >> 4) << 3) + (lane & 7)), bChunk = (uint32_t)((lane >> 3) & 1);

    const int nch = K >> 5;

    auto issue = [&](int kb) {
        const int k0 = kb << 5;
        const uint32_t sb = sbase + (kb % 3) * STAGE_B;
        #pragma unroll
        for (int i = 0; i < 6; i++) {
            const int t3 = i >> 1;
            const int rid = ((i & 1) << 8) + tid;
            const int row = rid >> 2, ch = rid & 3;
            cp16(sb + t3 * TILE_B + row * 80 + ch * 16, gbase[t3] + (size_t)row * K + k0 + ch * 8);
        }
        CP_COMMIT();
    };

    issue(0);
    if (1 < nch) issue(1);

    for (int kb = 0; kb < nch; kb++) {
        if (kb + 1 < nch) { CP_WAIT1(); } else { CP_WAIT0(); }
        __syncthreads();
        if (kb + 2 < nch) issue(kb + 2);

        const uint32_t sb = sbase + (kb % 3) * STAGE_B;
        const uint32_t sAh = sb, sAl = sb + TILE_B, sBh = sb + 2 * TILE_B;

        #pragma unroll
        for (int s = 0; s < 2; s++) {
            const uint32_t cOff = (2 * s) * 16;
            uint32_t ah[2][4], al[2][4], bh[8][2];
            #pragma unroll
            for (int mt = 0; mt < 2; mt++) {
                const uint32_t ad = (uint32_t)(warp_m + mt * 16 + aRow) * 80 + cOff + aChunk * 16;
                ldsm_x4(ah[mt][0], ah[mt][1], ah[mt][2], ah[mt][3], sAh + ad);
                ldsm_x4(al[mt][0], al[mt][1], al[mt][2], al[mt][3], sAl + ad);
            }
            #pragma unroll
            for (int p = 0; p < 4; p++) {
                const uint32_t bd = (uint32_t)(warp_n + p * 16 + bRow) * 80 + cOff + bChunk * 16;
                ldsm_x4(bh[2 * p][0], bh[2 * p][1], bh[2 * p + 1][0], bh[2 * p + 1][1], sBh + bd);
            }
            #pragma unroll
            for (int mt = 0; mt < 2; mt++)
                #pragma unroll
                for (int nt = 0; nt < 8; nt++) {
                    mma_f16(c[mt][nt], ah[mt], bh[nt]);
                    mma_f16(c[mt][nt], al[mt], bh[nt]);
                }
        }
    }
}

// ---------------------------------------------------------------------------
// Fused projection: Wq/Wk/Wv GEMM + rope/rmsnorm (q,k) + gated-ve (v).
// ---------------------------------------------------------------------------
__global__ __launch_bounds__(256) void gemm_proj(const __half* __restrict__ xh,
                                                 const __half* __restrict__ xl,
                                                 const __half* __restrict__ wqh,
                                                 const __half* __restrict__ wkh,
                                                 const __half* __restrict__ wvh,
                                                 const float* __restrict__ cs,
                                                 const float* __restrict__ sn,
                                                 const float* __restrict__ ve,
                                                 const float* __restrict__ gate,
                                                 __half* __restrict__ qph, __half* __restrict__ qpl,
                                                 __half* __restrict__ kph, __half* __restrict__ vph) {
    extern __shared__ char sm[];
    const int bx = blockIdx.x;
    const int bm = blockIdx.y * 128;
    const __half* Bh;
    int bn;
    if (bx < 8)       { Bh = wqh; bn = bx * 128; }
    else if (bx < 10) { Bh = wkh; bn = (bx - 8) * 128; }
    else              { Bh = wvh; bn = (bx - 10) * 128; }

    float c[2][8][4];
    gemm_mainloop(xh, xl, Bh, bm, bn, NE, smem_u32(sm), c);

    const int lane = threadIdx.x & 31, wid = threadIdx.x >> 5;
    const int warp_m = (wid & 3) * 32;
    const int gid = lane >> 2, t2 = (lane & 3) * 2;
    const int hh = (bn + (wid >> 2) * 64) / 64;

    if (bx < 10) {
        const bool isq = (bx < 8);
        #pragma unroll
        for (int mt = 0; mt < 2; mt++) {
            #pragma unroll
            for (int e = 0; e < 2; e++) {
                const int tg = bm + warp_m + mt * 16 + gid + e * 8;
                float y[8][2];
                float ss = 0.f;
                #pragma unroll
                for (int nt = 0; nt < 4; nt++) {
                    const float2 cc = *(const float2*)(cs + (size_t)tg * 32 + nt * 8 + t2);
                    const float2 s2 = *(const float2*)(sn + (size_t)tg * 32 + nt * 8 + t2);
                    #pragma unroll
                    for (int j = 0; j < 2; j++) {
                        const float x1 = c[mt][nt][e * 2 + j];
                        const float x2 = c[mt][nt + 4][e * 2 + j];
                        const float cv = j ? cc.y : cc.x;
                        const float sv = j ? s2.y : s2.x;
                        const float y1 = x1 * cv + x2 * sv;
                        const float y2 = -x1 * sv + x2 * cv;
                        y[nt][j] = y1; y[nt + 4][j] = y2;
                        ss += y1 * y1 + y2 * y2;
                    }
                }
                ss += __shfl_xor_sync(0xffffffffu, ss, 1);
                ss += __shfl_xor_sync(0xffffffffu, ss, 2);
                float rr = rsqrtf(ss * (1.f / 64.f) + 1e-6f);
                const int bb = tg >> 11, tt = tg & 2047;
                if (isq) {
                    rr *= 0.125f * 1.44269504088896f;
                    const size_t off = ((size_t)(bb * NH + hh) * Tt + tt) * 64;
                    #pragma unroll
                    for (int nt = 0; nt < 8; nt++) {
                        uint32_t hp, lp;
                        split2h(y[nt][0] * rr, y[nt][1] * rr, hp, lp);
                        *(uint32_t*)(qph + off + nt * 8 + t2) = hp;
                        *(uint32_t*)(qpl + off + nt * 8 + t2) = lp;
                    }
                } else {
                    const size_t off = ((size_t)(bb * NKV + hh) * Tt + tt) * 64;
                    #pragma unroll
                    for (int nt = 0; nt < 8; nt++)
                        *(uint32_t*)(kph + off + nt * 8 + t2) =
                            pack_h2(__float2half_rn(y[nt][0] * rr), __float2half_rn(y[nt][1] * rr));
                }
            }
        }
    } else {
        #pragma unroll
        for (int mt = 0; mt < 2; mt++) {
            #pragma unroll
            for (int e = 0; e < 2; e++) {
                const int tg = bm + warp_m + mt * 16 + gid + e * 8;
                const int bb = tg >> 11, tt = tg & 2047;
                const float gt = gate[tg * NKV + hh];
                const size_t off = ((size_t)(bb * NKV + hh) * Tt + tt) * 64;
                #pragma unroll
                for (int nt = 0; nt < 8; nt++) {
                    const float2 vv = *(const float2*)(ve + (size_t)tg * KVDIM + hh * 64 + nt * 8 + t2);
                    const float v0 = c[mt][nt][e * 2]     + gt * vv.x;
                    const float v1 = c[mt][nt][e * 2 + 1] + gt * vv.y;
                    *(uint32_t*)(vph + off + nt * 8 + t2) =
                        pack_h2(__float2half_rn(v0), __float2half_rn(v1));
                }
            }
        }
    }
}

// Generic GEMM (output projection, fp32 out)
__global__ __launch_bounds__(256) void gemm_mma(const __half* __restrict__ Ah,
                                                const __half* __restrict__ Al,
                                                const __half* __restrict__ Bh,
                                                float* __restrict__ C,
                                                int M, int N, int K) {
    extern __shared__ char sm[];
    const int bm = blockIdx.y * 128, bn = blockIdx.x * 128;
    float c[2][8][4];
    gemm_mainloop(Ah, Al, Bh, bm, bn, K, smem_u32(sm), c);

    const int lane = threadIdx.x & 31, wid = threadIdx.x >> 5;
    const int warp_m = (wid & 3) * 32, warp_n = (wid >> 2) * 64;
    const int gid = lane >> 2, t2 = (lane & 3) * 2;
    #pragma unroll
    for (int mt = 0; mt < 2; mt++) {
        const int r0 = bm + warp_m + mt * 16 + gid;
        #pragma unroll
        for (int nt = 0; nt < 8; nt++) {
            const int col = bn + warp_n + nt * 8 + t2;
            *(float2*)(C + (size_t)r0 * N + col)       = make_float2(c[mt][nt][0], c[mt][nt][1]);
            *(float2*)(C + (size_t)(r0 + 8) * N + col) = make_float2(c[mt][nt][2], c[mt][nt][3]);
        }
    }
}

// ---------------------------------------------------------------------------
// Windowed causal flash attention — fp16 2-MMA QK, hi-only PV, 3-stage pipeline
// ---------------------------------------------------------------------------
#define SROW 144
#define KVT  9216                   // 64 * 144
#define ASTAGE (2 * KVT)            // 18432 per stage
#define ATTN_SMEM (3 * ASTAGE)      // 55296 (3 stages)

__global__ __launch_bounds__(128) void attn_kernel(const __half* __restrict__ qh,
                                                   const __half* __restrict__ ql,
                                                   const __half* __restrict__ kh,
                                                   const __half* __restrict__ vh,
                                                   __half* __restrict__ Yh,
                                                   __half* __restrict__ Yl) {
    extern __shared__ char smA[];
    const uint32_t sbase = smem_u32(smA);

    const int tid = threadIdx.x, lane = tid & 31, w = tid >> 5;
    const int qs = (gridDim.x - 1 - blockIdx.x) * 64;   // heavy tiles first
    const int h = blockIdx.y, b = blockIdx.z;
    const int kvh = h >> 2;

    {
        const size_t qoff = ((size_t)(b * NH + h) * Tt + qs) * 64;
        #pragma unroll
        for (int i = 0; i < 4; i++) {
            const int cid = i * 128 + tid;
            const int row = cid >> 3, ch = cid & 7;
            cp16(sbase + row * SROW + ch * 16,       qh + qoff + row * 64 + ch * 8);
            cp16(sbase + KVT + row * SROW + ch * 16, ql + qoff + row * 64 + ch * 8);
        }
        CP_COMMIT();
        CP_WAIT0();
        __syncthreads();
    }
    uint32_t qah[4][4], qal[4][4];
    const uint32_t aRow = (uint32_t)(lane & 15), aCh = (uint32_t)(lane >> 4);
    #pragma unroll
    for (int s = 0; s < 4; s++) {
        const uint32_t ad = (uint32_t)(w * 16 + aRow) * SROW + s * 32 + aCh * 16;
        ldsm_x4(qah[s][0], qah[s][1], qah[s][2], qah[s][3], sbase + ad);
        ldsm_x4(qal[s][0], qal[s][1], qal[s][2], qal[s][3], sbase + KVT + ad);
    }
    __syncthreads();

    float o[8][4];
    #pragma unroll
    for (int nt = 0; nt < 8; nt++)
        #pragma unroll
        for (int e = 0; e < 4; e++) o[nt][e] = 0.f;
    float m0 = -1e30f, m1 = -1e30f, l0 = 0.f, l1 = 0.f;

    const int gid = lane >> 2, t2 = (lane & 3) * 2;
    const int r0 = qs + w * 16 + gid, r1 = r0 + 8;
    const int wrow = qs + w * 16;
    const uint32_t bRow = (uint32_t)(((lane >> 4) << 3) + (lane & 7));
    const uint32_t bCh = (uint32_t)((lane >> 3) & 1);
    const uint32_t vRow = (uint32_t)(lane & 15), vCh = (uint32_t)(lane >> 4);

    const int t0 = (qs >= WIN) ? (qs - WIN) : 0;
    const int nit = (qs - t0) / 64 + 1;
    const size_t kvbase = ((size_t)(b * NKV + kvh) * Tt) * 64;

    auto issue_kv = [&](int it) {
        const size_t kvoff = kvbase + (size_t)(t0 + it * 64) * 64;
        const uint32_t sb = sbase + (it % 3) * ASTAGE;
        #pragma unroll
        for (int i = 0; i < 4; i++) {
            const int cid = i * 128 + tid;
            const int row = cid >> 3, ch = cid & 7;
            const uint32_t so = row * SROW + ch * 16;
            const size_t go = kvoff + row * 64 + ch * 8;
            cp16(sb + so,       kh + go);
            cp16(sb + KVT + so, vh + go);
        }
        CP_COMMIT();
    };

    issue_kv(0);
    if (1 < nit) issue_kv(1);

    for (int it = 0; it < nit; it++) {
        const int ts = t0 + it * 64;
        if (it + 1 < nit) { CP_WAIT1(); } else { CP_WAIT0(); }
        __syncthreads();
        if (it + 2 < nit) issue_kv(it + 2);

        const uint32_t sb = sbase + (it % 3) * ASTAGE;
        const uint32_t aKh = sb, aVh = sb + KVT;

        float sc[8][4];
        #pragma unroll
        for (int nt = 0; nt < 8; nt++)
            #pragma unroll
            for (int e = 0; e < 4; e++) sc[nt][e] = 0.f;

        #pragma unroll
        for (int s = 0; s < 4; s++) {
            #pragma unroll
            for (int p = 0; p < 4; p++) {
                uint32_t h0, h1, h2, h3;
                const uint32_t bd = (uint32_t)(p * 16 + bRow) * SROW + s * 32 + bCh * 16;
                ldsm_x4(h0, h1, h2, h3, aKh + bd);
                uint32_t bha[2] = {h0, h1}, bhb[2] = {h2, h3};
                mma_f16(sc[2 * p],     qah[s], bha);
                mma_f16(sc[2 * p],     qal[s], bha);
                mma_f16(sc[2 * p + 1], qah[s], bhb);
                mma_f16(sc[2 * p + 1], qal[s], bhb);
            }
        }

        const bool needs_mask = (ts + 63 > wrow) || (wrow + 15 - ts > WIN);
        if (needs_mask) {
            #pragma unroll
            for (int nt = 0; nt < 8; nt++) {
                const int c0 = ts + nt * 8 + t2;
                const int c1 = c0 + 1;
                if (c0 > r0 || r0 - c0 > WIN) sc[nt][0] = -1e30f;
                if (c1 > r0 || r0 - c1 > WIN) sc[nt][1] = -1e30f;
                if (c0 > r1 || r1 - c0 > WIN) sc[nt][2] = -1e30f;
                if (c1 > r1 || r1 - c1 > WIN) sc[nt][3] = -1e30f;
            }
        }

        float ml0 = -1e30f, ml1 = -1e30f;
        #pragma unroll
        for (int nt = 0; nt < 8; nt++) {
            ml0 = fmaxf(ml0, fmaxf(sc[nt][0], sc[nt][1]));
            ml1 = fmaxf(ml1, fmaxf(sc[nt][2], sc[nt][3]));
        }
        ml0 = fmaxf(ml0, __shfl_xor_sync(0xffffffffu, ml0, 1));
        ml0 = fmaxf(ml0, __shfl_xor_sync(0xffffffffu, ml0, 2));
        ml1 = fmaxf(ml1, __shfl_xor_sync(0xffffffffu, ml1, 1));
        ml1 = fmaxf(ml1, __shfl_xor_sync(0xffffffffu, ml1, 2));

        const float mn0 = fmaxf(m0, ml0), mn1 = fmaxf(m1, ml1);
        const float cr0 = exp2f(m0 - mn0), cr1 = exp2f(m1 - mn1);
        l0 *= cr0; l1 *= cr1;
        #pragma unroll
        for (int nt = 0; nt < 8; nt++) {
            o[nt][0] *= cr0; o[nt][1] *= cr0;
            o[nt][2] *= cr1; o[nt][3] *= cr1;
        }
        m0 = mn0; m1 = mn1;

        #pragma unroll
        for (int kk = 0; kk < 4; kk++) {
            const float p00 = exp2f(sc[2 * kk][0] - m0), p01 = exp2f(sc[2 * kk][1] - m0);
            const float p02 = exp2f(sc[2 * kk][2] - m1), p03 = exp2f(sc[2 * kk][3] - m1);
            const float p10 = exp2f(sc[2 * kk + 1][0] - m0), p11 = exp2f(sc[2 * kk + 1][1] - m0);
            const float p12 = exp2f(sc[2 * kk + 1][2] - m1), p13 = exp2f(sc[2 * kk + 1][3] - m1);
            l0 += p00 + p01 + p10 + p11;
            l1 += p02 + p03 + p12 + p13;

            uint32_t pah[4];
            pah[0] = pack_h2(__float2half_rn(p00), __float2half_rn(p01));
            pah[1] = pack_h2(__float2half_rn(p02), __float2half_rn(p03));
            pah[2] = pack_h2(__float2half_rn(p10), __float2half_rn(p11));
            pah[3] = pack_h2(__float2half_rn(p12), __float2half_rn(p13));

            #pragma unroll
            for (int np = 0; np < 4; np++) {
                uint32_t v0, v1, v2, v3;
                const uint32_t vd = (uint32_t)(kk * 16 + vRow) * SROW + (np * 16 + vCh * 8) * 2;
                ldsm_x4t(v0, v1, v2, v3, aVh + vd);
                uint32_t bva[2] = {v0, v1}, bvb[2] = {v2, v3};
                mma_f16(o[2 * np],     pah, bva);
                mma_f16(o[2 * np + 1], pah, bvb);
            }
        }
    }

    l0 += __shfl_xor_sync(0xffffffffu, l0, 1);
    l0 += __shfl_xor_sync(0xffffffffu, l0, 2);
    l1 += __shfl_xor_sync(0xffffffffu, l1, 1);
    l1 += __shfl_xor_sync(0xffffffffu, l1, 2);
    const float i0 = 1.f / l0, i1 = 1.f / l1;

    const size_t y0o = (size_t)(b * Tt + r0) * QKDIM + h * HD;
    const size_t y1o = (size_t)(b * Tt + r1) * QKDIM + h * HD;
    #pragma unroll
    for (int nt = 0; nt < 8; nt++) {
        const int col = nt * 8 + t2;
        uint32_t hp, lp;
        split2h(o[nt][0] * i0, o[nt][1] * i0, hp, lp);
        *(uint32_t*)(Yh + y0o + col) = hp;
        *(uint32_t*)(Yl + y0o + col) = lp;
        split2h(o[nt][2] * i1, o[nt][3] * i1, hp, lp);
        *(uint32_t*)(Yh + y1o + col) = hp;
        *(uint32_t*)(Yl + y1o + col) = lp;
    }
}

// ---------------------------------------------------------------------------
extern "C" void kernel_launch(void* const* d_in, const int* in_sizes, int n_in,
                              void* d_out, int out_size) {
    const float* x  = (const float*)d_in[0];
    const float* ve = (const float*)d_in[1];
    const float* cs = (const float*)d_in[2];
    const float* sn = (const float*)d_in[3];
    const float* Wq = (const float*)d_in[4];
    const float* Wk = (const float*)d_in[5];
    const float* Wv = (const float*)d_in[6];
    const float* Wo = (const float*)d_in[7];
    const float* Wg = (const float*)d_in[8];
    float* out = (float*)d_out;

    __half *xh, *xl, *yh, *yl, *wqh, *wkh, *wvh, *woh;
    cudaGetSymbolAddress((void**)&xh, g_xh);  cudaGetSymbolAddress((void**)&xl, g_xl);
    cudaGetSymbolAddress((void**)&yh, g_yh);  cudaGetSymbolAddress((void**)&yl, g_yl);
    cudaGetSymbolAddress((void**)&wqh, g_wqh);
    cudaGetSymbolAddress((void**)&wkh, g_wkh);
    cudaGetSymbolAddress((void**)&wvh, g_wvh);
    cudaGetSymbolAddress((void**)&woh, g_woh);
    __half *qph, *qpl, *kph, *vph;
    cudaGetSymbolAddress((void**)&qph, g_qph); cudaGetSymbolAddress((void**)&qpl, g_qpl);
    cudaGetSymbolAddress((void**)&kph, g_kph);
    cudaGetSymbolAddress((void**)&vph, g_vph);
    float* gate;
    cudaGetSymbolAddress((void**)&gate, g_gate);

    cudaFuncSetAttribute(gemm_proj, cudaFuncAttributeMaxDynamicSharedMemorySize, GEMM_SMEM);
    cudaFuncSetAttribute(gemm_mma, cudaFuncAttributeMaxDynamicSharedMemorySize, GEMM_SMEM);
    cudaFuncSetAttribute(attn_kernel, cudaFuncAttributeMaxDynamicSharedMemorySize, ATTN_SMEM);

    const int n4 = BT * NE / 4;

    // Conversions + gate
    split_kernel<<<n4 / 256, 256>>>((const float4*)x, xh, xl, n4);
    tsplit_all<<<dim3(32, 32, 4), dim3(32, 8)>>>(Wq, Wk, Wv, Wo, wqh, wkh, wvh, woh);
    gate_kernel<<<BT / 8, 256>>>(x, Wg, gate);

    // Fused projection + rope/rmsnorm/gated-ve
    gemm_proj<<<dim3(12, BT / 128), 256, GEMM_SMEM>>>(xh, xl, wqh, wkh, wvh,
                                                      cs, sn, ve, gate,
                                                      qph, qpl, kph, vph);

    // attention
    attn_kernel<<<dim3(Tt / 64, NH, Bb), 128, ATTN_SMEM>>>(qph, qpl, kph, vph, yh, yl);

    // output projection
    gemm_mma<<<dim3(NE / 128, BT / 128), 256, GEMM_SMEM>>>(yh, yl, woh, out, BT, NE, NE);
}

// round 14
// speedup vs baseline: 1.0777x; 1.0777x over previous
#include <cuda_runtime.h>
#include <cuda_fp16.h>
#include <math.h>
#include <cstdint>

// Problem constants
#define Bb   2
#define Tt   2048
#define NE   1024
#define NH   16
#define NKV  4
#define HD   64
#define GC   32
#define WIN  1024
#define BT   (Bb*Tt)          // 4096
#define QKDIM (NH*HD)         // 1024
#define KVDIM (NKV*HD)        // 256

// fp16 split planes for GEMMs (A = hi+lo, B = hi only)
__device__ __align__(256) __half g_xh[BT * NE],  g_xl[BT * NE];
__device__ __align__(256) __half g_yh[BT * NE],  g_yl[BT * NE];
__device__ __align__(256) __half g_wqh[QKDIM * NE];
__device__ __align__(256) __half g_wkh[KVDIM * NE];
__device__ __align__(256) __half g_wvh[KVDIM * NE];
__device__ __align__(256) __half g_woh[NE * NE];

// fp16 planes for attention, head-major: q hi+lo, k/v hi only
__device__ __align__(256) __half g_qph[BT * QKDIM], g_qpl[BT * QKDIM];
__device__ __align__(256) __half g_kph[BT * KVDIM];
__device__ __align__(256) __half g_vph[BT * KVDIM];

// gate values: [BT][NKV]
__device__ float g_gate[BT * NKV];

// ---------------------------------------------------------------------------
// Helpers
// ---------------------------------------------------------------------------
__device__ __forceinline__ uint32_t smem_u32(const void* p) {
    uint32_t a;
    asm("{ .reg .u64 t; cvta.to.shared.u64 t, %1; cvt.u32.u64 %0, t; }" : "=r"(a) : "l"(p));
    return a;
}
__device__ __forceinline__ void cp16(uint32_t s, const void* g) {
    asm volatile("cp.async.cg.shared.global [%0], [%1], 16;" :: "r"(s), "l"(g));
}
#define CP_COMMIT() asm volatile("cp.async.commit_group;" ::: "memory")
#define CP_WAIT0()  asm volatile("cp.async.wait_group 0;" ::: "memory")

__device__ __forceinline__ void ldsm_x4(uint32_t& r0, uint32_t& r1, uint32_t& r2, uint32_t& r3,
                                        uint32_t addr) {
    asm volatile("ldmatrix.sync.aligned.m8n8.x4.shared.b16 {%0,%1,%2,%3}, [%4];"
                 : "=r"(r0), "=r"(r1), "=r"(r2), "=r"(r3) : "r"(addr));
}
__device__ __forceinline__ void ldsm_x4t(uint32_t& r0, uint32_t& r1, uint32_t& r2, uint32_t& r3,
                                         uint32_t addr) {
    asm volatile("ldmatrix.sync.aligned.m8n8.x4.trans.shared.b16 {%0,%1,%2,%3}, [%4];"
                 : "=r"(r0), "=r"(r1), "=r"(r2), "=r"(r3) : "r"(addr));
}
__device__ __forceinline__ void mma_f16(float* c, const uint32_t* a, const uint32_t* b) {
    asm volatile("mma.sync.aligned.m16n8k16.row.col.f32.f16.f16.f32 "
                 "{%0,%1,%2,%3}, {%4,%5,%6,%7}, {%8,%9}, {%0,%1,%2,%3};"
                 : "+f"(c[0]), "+f"(c[1]), "+f"(c[2]), "+f"(c[3])
                 : "r"(a[0]), "r"(a[1]), "r"(a[2]), "r"(a[3]), "r"(b[0]), "r"(b[1]));
}
__device__ __forceinline__ uint32_t pack_h2(__half a, __half b) {
    __half2 t = __halves2half2(a, b);
    return *reinterpret_cast<uint32_t*>(&t);
}
__device__ __forceinline__ void split2h(float a, float b, uint32_t& h, uint32_t& l) {
    __half ha = __float2half_rn(a), hb = __float2half_rn(b);
    h = pack_h2(ha, hb);
    l = pack_h2(__float2half_rn(a - __half2float(ha)),
                __float2half_rn(b - __half2float(hb)));
}
__device__ __forceinline__ float warp_sum(float v) {
    #pragma unroll
    for (int off = 16; off; off >>= 1) v += __shfl_xor_sync(0xffffffffu, v, off);
    return v;
}

// ---------------------------------------------------------------------------
// Split fp32 -> fp16 hi/lo planes
// ---------------------------------------------------------------------------
__global__ __launch_bounds__(256) void split_kernel(const float4* __restrict__ in,
                                                    __half* __restrict__ hi,
                                                    __half* __restrict__ lo,
                                                    int n4) {
    int i = blockIdx.x * 256 + threadIdx.x;
    if (i >= n4) return;
    float4 v = in[i];
    float a[4] = {v.x, v.y, v.z, v.w};
    __half h[4], l[4];
    #pragma unroll
    for (int j = 0; j < 4; j++) {
        h[j] = __float2half_rn(a[j]);
        l[j] = __float2half_rn(a[j] - __half2float(h[j]));
    }
    __half2* h2 = (__half2*)(hi + 4 * (size_t)i);
    __half2* l2 = (__half2*)(lo + 4 * (size_t)i);
    h2[0] = __halves2half2(h[0], h[1]);
    h2[1] = __halves2half2(h[2], h[3]);
    l2[0] = __halves2half2(l[0], l[1]);
    l2[1] = __halves2half2(l[2], l[3]);
}

// Merged transpose for all 4 weights (z-select), fp16 hi-plane only.
__global__ __launch_bounds__(256) void tsplit_all(const float* __restrict__ Wq,
                                                  const float* __restrict__ Wk,
                                                  const float* __restrict__ Wv,
                                                  const float* __restrict__ Wo,
                                                  __half* __restrict__ qh_, __half* __restrict__ kh_,
                                                  __half* __restrict__ vh_, __half* __restrict__ oh_) {
    const int z = blockIdx.z;
    const float* W; __half* hi; int Ncols;
    if (z == 0)      { W = Wq; hi = qh_; Ncols = QKDIM; }
    else if (z == 1) { W = Wk; hi = kh_; Ncols = KVDIM; }
    else if (z == 2) { W = Wv; hi = vh_; Ncols = KVDIM; }
    else             { W = Wo; hi = oh_; Ncols = NE; }
    if (blockIdx.x * 32 >= Ncols) return;

    __shared__ float t[32][33];
    const int n0 = blockIdx.x * 32, k0 = blockIdx.y * 32;
    const int tx = threadIdx.x, ty = threadIdx.y;   // 32 x 8
    #pragma unroll
    for (int j = 0; j < 32; j += 8)
        t[ty + j][tx] = W[(size_t)(k0 + ty + j) * Ncols + n0 + tx];
    __syncthreads();
    #pragma unroll
    for (int j = 0; j < 32; j += 8) {
        size_t o = (size_t)(n0 + ty + j) * NE + k0 + tx;
        hi[o] = __float2half_rn(t[tx][ty + j]);
    }
}

// Gate precompute
__global__ __launch_bounds__(256) void gate_kernel(const float* __restrict__ x,
                                                   const float* __restrict__ Wg,
                                                   float* __restrict__ gate) {
    const int bt = blockIdx.x * 8 + (threadIdx.x >> 5);
    const int lane = threadIdx.x & 31;
    const float xv = x[(size_t)bt * NE + lane];
    #pragma unroll
    for (int kvh = 0; kvh < NKV; kvh++) {
        float dot = warp_sum(xv * Wg[lane * NKV + kvh]);
        if (lane == 0) gate[bt * NKV + kvh] = 2.f / (1.f + __expf(-dot));
    }
}

// ---------------------------------------------------------------------------
// mma.sync 2-MMA fp16 GEMM mainloop.
// K-chunk 64 (128B rows @ 144B stride), 2-stage cp.async, 1 sync/chunk.
// ---------------------------------------------------------------------------
#define TILE144  18432              // 128 rows * 144B
#define STG64    (3 * TILE144)      // 55296 per stage
#define GEMM_SMEM (2 * STG64)       // 110592

__device__ __forceinline__ void gemm_mainloop(const __half* __restrict__ Ah,
                                              const __half* __restrict__ Al,
                                              const __half* __restrict__ Bh,
                                              int bm, int bn, int K,
                                              uint32_t sbase, float c[2][8][4]) {
    const int tid = threadIdx.x;
    const int lane = tid & 31, wid = tid >> 5;
    const int warp_m = (wid & 3) * 32;
    const int warp_n = (wid >> 2) * 64;

    const __half* gbase[3] = {Ah + (size_t)bm * K, Al + (size_t)bm * K, Bh + (size_t)bn * K};

    #pragma unroll
    for (int mt = 0; mt < 2; mt++)
        #pragma unroll
        for (int nt = 0; nt < 8; nt++)
            #pragma unroll
            for (int e = 0; e < 4; e++) c[mt][nt][e] = 0.f;

    const uint32_t aRow = (uint32_t)(lane & 15), aChunk = (uint32_t)(lane >> 4);
    const uint32_t bRow = (uint32_t)(((lane >> 4) << 3) + (lane & 7)), bChunk = (uint32_t)((lane >> 3) & 1);

    const int nch = K >> 6;             // K-chunks of 64

    auto issue = [&](int kb) {
        const int k0 = kb << 6;
        const uint32_t sb = sbase + (kb & 1) * STG64;
        #pragma unroll
        for (int i = 0; i < 12; i++) {
            const int t3 = i >> 2;
            const int rid = ((i & 3) << 8) + tid;      // 0..1023 per tile
            const int row = rid >> 3, ch = rid & 7;
            cp16(sb + t3 * TILE144 + row * 144 + ch * 16,
                 gbase[t3] + (size_t)row * K + k0 + ch * 8);
        }
        CP_COMMIT();
    };

    issue(0);

    for (int kb = 0; kb < nch; kb++) {
        CP_WAIT0();
        __syncthreads();
        if (kb + 1 < nch) issue(kb + 1);

        const uint32_t sb = sbase + (kb & 1) * STG64;
        const uint32_t sAh = sb, sAl = sb + TILE144, sBh = sb + 2 * TILE144;

        #pragma unroll
        for (int s = 0; s < 4; s++) {
            const uint32_t cOff = s * 32;
            uint32_t ah[2][4], al[2][4], bh[8][2];
            #pragma unroll
            for (int mt = 0; mt < 2; mt++) {
                const uint32_t ad = (uint32_t)(warp_m + mt * 16 + aRow) * 144 + cOff + aChunk * 16;
                ldsm_x4(ah[mt][0], ah[mt][1], ah[mt][2], ah[mt][3], sAh + ad);
                ldsm_x4(al[mt][0], al[mt][1], al[mt][2], al[mt][3], sAl + ad);
            }
            #pragma unroll
            for (int p = 0; p < 4; p++) {
                const uint32_t bd = (uint32_t)(warp_n + p * 16 + bRow) * 144 + cOff + bChunk * 16;
                ldsm_x4(bh[2 * p][0], bh[2 * p][1], bh[2 * p + 1][0], bh[2 * p + 1][1], sBh + bd);
            }
            #pragma unroll
            for (int mt = 0; mt < 2; mt++)
                #pragma unroll
                for (int nt = 0; nt < 8; nt++) {
                    mma_f16(c[mt][nt], ah[mt], bh[nt]);
                    mma_f16(c[mt][nt], al[mt], bh[nt]);
                }
        }
    }
}

// ---------------------------------------------------------------------------
// Fused projection: Wq/Wk/Wv GEMM + rope/rmsnorm (q,k) + gated-ve (v).
// ---------------------------------------------------------------------------
__global__ __launch_bounds__(256) void gemm_proj(const __half* __restrict__ xh,
                                                 const __half* __restrict__ xl,
                                                 const __half* __restrict__ wqh,
                                                 const __half* __restrict__ wkh,
                                                 const __half* __restrict__ wvh,
                                                 const float* __restrict__ cs,
                                                 const float* __restrict__ sn,
                                                 const float* __restrict__ ve,
                                                 const float* __restrict__ gate,
                                                 __half* __restrict__ qph, __half* __restrict__ qpl,
                                                 __half* __restrict__ kph, __half* __restrict__ vph) {
    extern __shared__ char sm[];
    const int bx = blockIdx.x;
    const int bm = blockIdx.y * 128;
    const __half* Bh;
    int bn;
    if (bx < 8)       { Bh = wqh; bn = bx * 128; }
    else if (bx < 10) { Bh = wkh; bn = (bx - 8) * 128; }
    else              { Bh = wvh; bn = (bx - 10) * 128; }

    float c[2][8][4];
    gemm_mainloop(xh, xl, Bh, bm, bn, NE, smem_u32(sm), c);

    const int lane = threadIdx.x & 31, wid = threadIdx.x >> 5;
    const int warp_m = (wid & 3) * 32;
    const int gid = lane >> 2, t2 = (lane & 3) * 2;
    const int hh = (bn + (wid >> 2) * 64) / 64;

    if (bx < 10) {
        const bool isq = (bx < 8);
        #pragma unroll
        for (int mt = 0; mt < 2; mt++) {
            #pragma unroll
            for (int e = 0; e < 2; e++) {
                const int tg = bm + warp_m + mt * 16 + gid + e * 8;
                float y[8][2];
                float ss = 0.f;
                #pragma unroll
                for (int nt = 0; nt < 4; nt++) {
                    const float2 cc = *(const float2*)(cs + (size_t)tg * 32 + nt * 8 + t2);
                    const float2 s2 = *(const float2*)(sn + (size_t)tg * 32 + nt * 8 + t2);
                    #pragma unroll
                    for (int j = 0; j < 2; j++) {
                        const float x1 = c[mt][nt][e * 2 + j];
                        const float x2 = c[mt][nt + 4][e * 2 + j];
                        const float cv = j ? cc.y : cc.x;
                        const float sv = j ? s2.y : s2.x;
                        const float y1 = x1 * cv + x2 * sv;
                        const float y2 = -x1 * sv + x2 * cv;
                        y[nt][j] = y1; y[nt + 4][j] = y2;
                        ss += y1 * y1 + y2 * y2;
                    }
                }
                ss += __shfl_xor_sync(0xffffffffu, ss, 1);
                ss += __shfl_xor_sync(0xffffffffu, ss, 2);
                float rr = rsqrtf(ss * (1.f / 64.f) + 1e-6f);
                const int bb = tg >> 11, tt = tg & 2047;
                if (isq) {
                    rr *= 0.125f * 1.44269504088896f;
                    const size_t off = ((size_t)(bb * NH + hh) * Tt + tt) * 64;
                    #pragma unroll
                    for (int nt = 0; nt < 8; nt++) {
                        uint32_t hp, lp;
                        split2h(y[nt][0] * rr, y[nt][1] * rr, hp, lp);
                        *(uint32_t*)(qph + off + nt * 8 + t2) = hp;
                        *(uint32_t*)(qpl + off + nt * 8 + t2) = lp;
                    }
                } else {
                    const size_t off = ((size_t)(bb * NKV + hh) * Tt + tt) * 64;
                    #pragma unroll
                    for (int nt = 0; nt < 8; nt++)
                        *(uint32_t*)(kph + off + nt * 8 + t2) =
                            pack_h2(__float2half_rn(y[nt][0] * rr), __float2half_rn(y[nt][1] * rr));
                }
            }
        }
    } else {
        #pragma unroll
        for (int mt = 0; mt < 2; mt++) {
            #pragma unroll
            for (int e = 0; e < 2; e++) {
                const int tg = bm + warp_m + mt * 16 + gid + e * 8;
                const int bb = tg >> 11, tt = tg & 2047;
                const float gt = gate[tg * NKV + hh];
                const size_t off = ((size_t)(bb * NKV + hh) * Tt + tt) * 64;
                #pragma unroll
                for (int nt = 0; nt < 8; nt++) {
                    const float2 vv = *(const float2*)(ve + (size_t)tg * KVDIM + hh * 64 + nt * 8 + t2);
                    const float v0 = c[mt][nt][e * 2]     + gt * vv.x;
                    const float v1 = c[mt][nt][e * 2 + 1] + gt * vv.y;
                    *(uint32_t*)(vph + off + nt * 8 + t2) =
                        pack_h2(__float2half_rn(v0), __float2half_rn(v1));
                }
            }
        }
    }
}

// Generic GEMM (output projection, fp32 out)
__global__ __launch_bounds__(256) void gemm_mma(const __half* __restrict__ Ah,
                                                const __half* __restrict__ Al,
                                                const __half* __restrict__ Bh,
                                                float* __restrict__ C,
                                                int M, int N, int K) {
    extern __shared__ char sm[];
    const int bm = blockIdx.y * 128, bn = blockIdx.x * 128;
    float c[2][8][4];
    gemm_mainloop(Ah, Al, Bh, bm, bn, K, smem_u32(sm), c);

    const int lane = threadIdx.x & 31, wid = threadIdx.x >> 5;
    const int warp_m = (wid & 3) * 32, warp_n = (wid >> 2) * 64;
    const int gid = lane >> 2, t2 = (lane & 3) * 2;
    #pragma unroll
    for (int mt = 0; mt < 2; mt++) {
        const int r0 = bm + warp_m + mt * 16 + gid;
        #pragma unroll
        for (int nt = 0; nt < 8; nt++) {
            const int col = bn + warp_n + nt * 8 + t2;
            *(float2*)(C + (size_t)r0 * N + col)       = make_float2(c[mt][nt][0], c[mt][nt][1]);
            *(float2*)(C + (size_t)(r0 + 8) * N + col) = make_float2(c[mt][nt][2], c[mt][nt][3]);
        }
    }
}

// ---------------------------------------------------------------------------
// Windowed causal flash attention — fp16 2-MMA QK, hi-only PV, 2-stage (R12)
// ---------------------------------------------------------------------------
#define SROW 144
#define KVT  9216                   // 64 * 144
#define ASTAGE (2 * KVT)            // 18432 per stage
#define ATTN_SMEM (2 * ASTAGE)      // 36864

__global__ __launch_bounds__(128) void attn_kernel(const __half* __restrict__ qh,
                                                   const __half* __restrict__ ql,
                                                   const __half* __restrict__ kh,
                                                   const __half* __restrict__ vh,
                                                   __half* __restrict__ Yh,
                                                   __half* __restrict__ Yl) {
    extern __shared__ char smA[];
    const uint32_t sbase = smem_u32(smA);

    const int tid = threadIdx.x, lane = tid & 31, w = tid >> 5;
    const int qs = (gridDim.x - 1 - blockIdx.x) * 64;   // heavy tiles first
    const int h = blockIdx.y, b = blockIdx.z;
    const int kvh = h >> 2;

    {
        const size_t qoff = ((size_t)(b * NH + h) * Tt + qs) * 64;
        #pragma unroll
        for (int i = 0; i < 4; i++) {
            const int cid = i * 128 + tid;
            const int row = cid >> 3, ch = cid & 7;
            cp16(sbase + row * SROW + ch * 16,       qh + qoff + row * 64 + ch * 8);
            cp16(sbase + KVT + row * SROW + ch * 16, ql + qoff + row * 64 + ch * 8);
        }
        CP_COMMIT();
        CP_WAIT0();
        __syncthreads();
    }
    uint32_t qah[4][4], qal[4][4];
    const uint32_t aRow = (uint32_t)(lane & 15), aCh = (uint32_t)(lane >> 4);
    #pragma unroll
    for (int s = 0; s < 4; s++) {
        const uint32_t ad = (uint32_t)(w * 16 + aRow) * SROW + s * 32 + aCh * 16;
        ldsm_x4(qah[s][0], qah[s][1], qah[s][2], qah[s][3], sbase + ad);
        ldsm_x4(qal[s][0], qal[s][1], qal[s][2], qal[s][3], sbase + KVT + ad);
    }
    __syncthreads();

    float o[8][4];
    #pragma unroll
    for (int nt = 0; nt < 8; nt++)
        #pragma unroll
        for (int e = 0; e < 4; e++) o[nt][e] = 0.f;
    float m0 = -1e30f, m1 = -1e30f, l0 = 0.f, l1 = 0.f;

    const int gid = lane >> 2, t2 = (lane & 3) * 2;
    const int r0 = qs + w * 16 + gid, r1 = r0 + 8;
    const int wrow = qs + w * 16;
    const uint32_t bRow = (uint32_t)(((lane >> 4) << 3) + (lane & 7));
    const uint32_t bCh = (uint32_t)((lane >> 3) & 1);
    const uint32_t vRow = (uint32_t)(lane & 15), vCh = (uint32_t)(lane >> 4);

    const int t0 = (qs >= WIN) ? (qs - WIN) : 0;
    const int nit = (qs - t0) / 64 + 1;
    const size_t kvbase = ((size_t)(b * NKV + kvh) * Tt) * 64;

    auto issue_kv = [&](int it) {
        const size_t kvoff = kvbase + (size_t)(t0 + it * 64) * 64;
        const uint32_t sb = sbase + (it & 1) * ASTAGE;
        #pragma unroll
        for (int i = 0; i < 4; i++) {
            const int cid = i * 128 + tid;
            const int row = cid >> 3, ch = cid & 7;
            const uint32_t so = row * SROW + ch * 16;
            const size_t go = kvoff + row * 64 + ch * 8;
            cp16(sb + so,       kh + go);
            cp16(sb + KVT + so, vh + go);
        }
        CP_COMMIT();
    };

    issue_kv(0);

    for (int it = 0; it < nit; it++) {
        const int ts = t0 + it * 64;
        CP_WAIT0();
        __syncthreads();
        if (it + 1 < nit) issue_kv(it + 1);

        const uint32_t sb = sbase + (it & 1) * ASTAGE;
        const uint32_t aKh = sb, aVh = sb + KVT;

        float sc[8][4];
        #pragma unroll
        for (int nt = 0; nt < 8; nt++)
            #pragma unroll
            for (int e = 0; e < 4; e++) sc[nt][e] = 0.f;

        #pragma unroll
        for (int s = 0; s < 4; s++) {
            #pragma unroll
            for (int p = 0; p < 4; p++) {
                uint32_t h0, h1, h2, h3;
                const uint32_t bd = (uint32_t)(p * 16 + bRow) * SROW + s * 32 + bCh * 16;
                ldsm_x4(h0, h1, h2, h3, aKh + bd);
                uint32_t bha[2] = {h0, h1}, bhb[2] = {h2, h3};
                mma_f16(sc[2 * p],     qah[s], bha);
                mma_f16(sc[2 * p],     qal[s], bha);
                mma_f16(sc[2 * p + 1], qah[s], bhb);
                mma_f16(sc[2 * p + 1], qal[s], bhb);
            }
        }

        const bool needs_mask = (ts + 63 > wrow) || (wrow + 15 - ts > WIN);
        if (needs_mask) {
            #pragma unroll
            for (int nt = 0; nt < 8; nt++) {
                const int c0 = ts + nt * 8 + t2;
                const int c1 = c0 + 1;
                if (c0 > r0 || r0 - c0 > WIN) sc[nt][0] = -1e30f;
                if (c1 > r0 || r0 - c1 > WIN) sc[nt][1] = -1e30f;
                if (c0 > r1 || r1 - c0 > WIN) sc[nt][2] = -1e30f;
                if (c1 > r1 || r1 - c1 > WIN) sc[nt][3] = -1e30f;
            }
        }

        float ml0 = -1e30f, ml1 = -1e30f;
        #pragma unroll
        for (int nt = 0; nt < 8; nt++) {
            ml0 = fmaxf(ml0, fmaxf(sc[nt][0], sc[nt][1]));
            ml1 = fmaxf(ml1, fmaxf(sc[nt][2], sc[nt][3]));
        }
        ml0 = fmaxf(ml0, __shfl_xor_sync(0xffffffffu, ml0, 1));
        ml0 = fmaxf(ml0, __shfl_xor_sync(0xffffffffu, ml0, 2));
        ml1 = fmaxf(ml1, __shfl_xor_sync(0xffffffffu, ml1, 1));
        ml1 = fmaxf(ml1, __shfl_xor_sync(0xffffffffu, ml1, 2));

        const float mn0 = fmaxf(m0, ml0), mn1 = fmaxf(m1, ml1);
        const float cr0 = exp2f(m0 - mn0), cr1 = exp2f(m1 - mn1);
        l0 *= cr0; l1 *= cr1;
        #pragma unroll
        for (int nt = 0; nt < 8; nt++) {
            o[nt][0] *= cr0; o[nt][1] *= cr0;
            o[nt][2] *= cr1; o[nt][3] *= cr1;
        }
        m0 = mn0; m1 = mn1;

        #pragma unroll
        for (int kk = 0; kk < 4; kk++) {
            const float p00 = exp2f(sc[2 * kk][0] - m0), p01 = exp2f(sc[2 * kk][1] - m0);
            const float p02 = exp2f(sc[2 * kk][2] - m1), p03 = exp2f(sc[2 * kk][3] - m1);
            const float p10 = exp2f(sc[2 * kk + 1][0] - m0), p11 = exp2f(sc[2 * kk + 1][1] - m0);
            const float p12 = exp2f(sc[2 * kk + 1][2] - m1), p13 = exp2f(sc[2 * kk + 1][3] - m1);
            l0 += p00 + p01 + p10 + p11;
            l1 += p02 + p03 + p12 + p13;

            uint32_t pah[4];
            pah[0] = pack_h2(__float2half_rn(p00), __float2half_rn(p01));
            pah[1] = pack_h2(__float2half_rn(p02), __float2half_rn(p03));
            pah[2] = pack_h2(__float2half_rn(p10), __float2half_rn(p11));
            pah[3] = pack_h2(__float2half_rn(p12), __float2half_rn(p13));

            #pragma unroll
            for (int np = 0; np < 4; np++) {
                uint32_t v0, v1, v2, v3;
                const uint32_t vd = (uint32_t)(kk * 16 + vRow) * SROW + (np * 16 + vCh * 8) * 2;
                ldsm_x4t(v0, v1, v2, v3, aVh + vd);
                uint32_t bva[2] = {v0, v1}, bvb[2] = {v2, v3};
                mma_f16(o[2 * np],     pah, bva);
                mma_f16(o[2 * np + 1], pah, bvb);
            }
        }
    }

    l0 += __shfl_xor_sync(0xffffffffu, l0, 1);
    l0 += __shfl_xor_sync(0xffffffffu, l0, 2);
    l1 += __shfl_xor_sync(0xffffffffu, l1, 1);
    l1 += __shfl_xor_sync(0xffffffffu, l1, 2);
    const float i0 = 1.f / l0, i1 = 1.f / l1;

    const size_t y0o = (size_t)(b * Tt + r0) * QKDIM + h * HD;
    const size_t y1o = (size_t)(b * Tt + r1) * QKDIM + h * HD;
    #pragma unroll
    for (int nt = 0; nt < 8; nt++) {
        const int col = nt * 8 + t2;
        uint32_t hp, lp;
        split2h(o[nt][0] * i0, o[nt][1] * i0, hp, lp);
        *(uint32_t*)(Yh + y0o + col) = hp;
        *(uint32_t*)(Yl + y0o + col) = lp;
        split2h(o[nt][2] * i1, o[nt][3] * i1, hp, lp);
        *(uint32_t*)(Yh + y1o + col) = hp;
        *(uint32_t*)(Yl + y1o + col) = lp;
    }
}

// ---------------------------------------------------------------------------
extern "C" void kernel_launch(void* const* d_in, const int* in_sizes, int n_in,
                              void* d_out, int out_size) {
    const float* x  = (const float*)d_in[0];
    const float* ve = (const float*)d_in[1];
    const float* cs = (const float*)d_in[2];
    const float* sn = (const float*)d_in[3];
    const float* Wq = (const float*)d_in[4];
    const float* Wk = (const float*)d_in[5];
    const float* Wv = (const float*)d_in[6];
    const float* Wo = (const float*)d_in[7];
    const float* Wg = (const float*)d_in[8];
    float* out = (float*)d_out;

    __half *xh, *xl, *yh, *yl, *wqh, *wkh, *wvh, *woh;
    cudaGetSymbolAddress((void**)&xh, g_xh);  cudaGetSymbolAddress((void**)&xl, g_xl);
    cudaGetSymbolAddress((void**)&yh, g_yh);  cudaGetSymbolAddress((void**)&yl, g_yl);
    cudaGetSymbolAddress((void**)&wqh, g_wqh);
    cudaGetSymbolAddress((void**)&wkh, g_wkh);
    cudaGetSymbolAddress((void**)&wvh, g_wvh);
    cudaGetSymbolAddress((void**)&woh, g_woh);
    __half *qph, *qpl, *kph, *vph;
    cudaGetSymbolAddress((void**)&qph, g_qph); cudaGetSymbolAddress((void**)&qpl, g_qpl);
    cudaGetSymbolAddress((void**)&kph, g_kph);
    cudaGetSymbolAddress((void**)&vph, g_vph);
    float* gate;
    cudaGetSymbolAddress((void**)&gate, g_gate);

    cudaFuncSetAttribute(gemm_proj, cudaFuncAttributeMaxDynamicSharedMemorySize, GEMM_SMEM);
    cudaFuncSetAttribute(gemm_mma, cudaFuncAttributeMaxDynamicSharedMemorySize, GEMM_SMEM);
    cudaFuncSetAttribute(attn_kernel, cudaFuncAttributeMaxDynamicSharedMemorySize, ATTN_SMEM);

    const int n4 = BT * NE / 4;

    // Conversions + gate
    split_kernel<<<n4 / 256, 256>>>((const float4*)x, xh, xl, n4);
    tsplit_all<<<dim3(32, 32, 4), dim3(32, 8)>>>(Wq, Wk, Wv, Wo, wqh, wkh, wvh, woh);
    gate_kernel<<<BT / 8, 256>>>(x, Wg, gate);

    // Fused projection + rope/rmsnorm/gated-ve
    gemm_proj<<<dim3(12, BT / 128), 256, GEMM_SMEM>>>(xh, xl, wqh, wkh, wvh,
                                                      cs, sn, ve, gate,
                                                      qph, qpl, kph, vph);

    // attention
    attn_kernel<<<dim3(Tt / 64, NH, Bb), 128, ATTN_SMEM>>>(qph, qpl, kph, vph, yh, yl);

    // output projection
    gemm_mma<<<dim3(NE / 128, BT / 128), 256, GEMM_SMEM>>>(yh, yl, woh, out, BT, NE, NE);
}